// round 12
// baseline (speedup 1.0000x reference)
#include <cuda_runtime.h>
#include <math.h>
#include <stdint.h>

#define N_QUBITS 10
#define N_LAYERS 4
#define DIM 1024
#define IN_F 512
#define OUT_F 64
#define BATCH 4096

// Scratch for the intermediate h = relu(x @ W_pre^T + b_pre): 4096 x 1024 fp32 = 16 MB
__device__ float g_h[BATCH * DIM];

// ---------------------------------------------------------------------------
// f32x2 packed-math helpers (FFMA2: one issue slot, two FMAs)
// ---------------------------------------------------------------------------
#define PACK_F32X2(out, lo, hi) \
    asm("mov.b64 %0, {%1, %2};" : "=l"(out) : "r"(lo), "r"(hi))
#define UNPACK_F32X2(lo, hi, in) \
    asm("mov.b64 {%0, %1}, %2;" : "=r"(lo), "=r"(hi) : "l"(in))
#define FMA_F32X2(d, a, b, c) \
    asm("fma.rn.f32x2 %0, %1, %2, %3;" : "=l"(d) : "l"(a), "l"(b), "l"(c))

// Per-element named barrier: element e = warps 4e..4e+3 (128 threads each).
// Barrier 0 is reserved for __syncthreads (CTA-wide setup syncs).
#define ELEM_BAR(e) \
    asm volatile("bar.sync %0, %1;" :: "r"((e) + 1), "r"(128) : "memory")

// Bank-conflict swizzle for the psi state array (8B elements): fold address
// bits 6..4 into bits 3..1. Involution (sw(sw(i)) == i), pure layout change.
// Makes group-0/1/2 passes conflict-free and group-3 2-way (was 8-way).
#define PSISW(i) ((i) ^ (((i) >> 3) & 0x0E))

// ---------------------------------------------------------------------------
// tf32 helpers
// ---------------------------------------------------------------------------
__device__ __forceinline__ uint32_t f2tf32(float x) {
    uint32_t r;
    asm("cvt.rna.tf32.f32 %0, %1;" : "=r"(r) : "f"(x));
    return r;
}

__device__ __forceinline__ void split_tf32(float x, uint32_t& hi, uint32_t& lo) {
    hi = f2tf32(x);
    lo = f2tf32(x - __uint_as_float(hi));
}

// D(16x8) += A(16x8) * B(8x8), tf32 inputs, fp32 accumulate.
__device__ __forceinline__ void mma_tf32(float* d, const uint32_t* a, const uint32_t* b) {
    asm volatile(
        "mma.sync.aligned.m16n8k8.row.col.f32.tf32.tf32.f32 "
        "{%0,%1,%2,%3}, {%4,%5,%6,%7}, {%8,%9}, {%0,%1,%2,%3};"
        : "+f"(d[0]), "+f"(d[1]), "+f"(d[2]), "+f"(d[3])
        : "r"(a[0]), "r"(a[1]), "r"(a[2]), "r"(a[3]), "r"(b[0]), "r"(b[1]));
}

__device__ __forceinline__ void cp_async16(uint32_t smem_addr, const void* gptr) {
    asm volatile("cp.async.cg.shared.global [%0], [%1], 16;" ::"r"(smem_addr), "l"(gptr));
}
__device__ __forceinline__ void cp_async_commit() {
    asm volatile("cp.async.commit_group;");
}
__device__ __forceinline__ void cp_async_wait_all() {
    asm volatile("cp.async.wait_group 0;");
}

// ---------------------------------------------------------------------------
// Kernel 1: fused GEMM + bias + ReLU via split-tf32 tensor-core mma.
// C[4096,1024] = relu(A[4096,512] @ W[1024,512]^T + bias).
// CTA tile 128(M) x 64(N), BK=16, 256 threads (8 warps, warp tile 32x32).
// cp.async double-buffered smem, stride-20 row pad (conflict-free, 16B-aligned).
// ONE barrier per K-tile (top-of-iteration wait+sync fences both directions).
// Split: C += Alo*Bhi + Ahi*Blo + Ahi*Bhi  (input error ~2^-21 << 1e-3).
// ---------------------------------------------------------------------------
#define BM 128
#define BN 64
#define BK 16
#define ASTRIDE 20
#define NTILES_K (IN_F / BK)   // 32

__global__ __launch_bounds__(256, 2)
void gemm_relu_tc_kernel(const float* __restrict__ A,
                         const float* __restrict__ B,
                         const float* __restrict__ bias,
                         float* __restrict__ C) {
    __shared__ float As[2][BM * ASTRIDE];
    __shared__ float Bs[2][BN * ASTRIDE];

    const int tid  = threadIdx.x;
    const int lane = tid & 31;
    const int wid  = tid >> 5;
    const int g    = lane >> 2;
    const int t    = lane & 3;

    const int bm = blockIdx.y * BM;
    const int bn = blockIdx.x * BN;

    const int warp_m = (wid & 3) * 32;
    const int warp_n = (wid >> 2) * 32;

    const int arow = tid >> 1;
    const int ac4  = (tid & 1) * 8;
    const int brow = tid >> 2;
    const int bc4  = (tid & 3) * 4;

    const float* gA = A + (size_t)(bm + arow) * IN_F + ac4;
    const float* gB = B + (size_t)(bn + brow) * IN_F + bc4;

    uint32_t sA0 = (uint32_t)__cvta_generic_to_shared(&As[0][arow * ASTRIDE + ac4]);
    uint32_t sA1 = (uint32_t)__cvta_generic_to_shared(&As[1][arow * ASTRIDE + ac4]);
    uint32_t sB0 = (uint32_t)__cvta_generic_to_shared(&Bs[0][brow * ASTRIDE + bc4]);
    uint32_t sB1 = (uint32_t)__cvta_generic_to_shared(&Bs[1][brow * ASTRIDE + bc4]);

    float acc[2][4][4];
#pragma unroll
    for (int i = 0; i < 2; i++)
#pragma unroll
        for (int j = 0; j < 4; j++)
#pragma unroll
            for (int c = 0; c < 4; c++) acc[i][j][c] = 0.0f;

    cp_async16(sA0, gA);
    cp_async16(sA0 + 16, gA + 4);
    cp_async16(sB0, gB);
    cp_async_commit();

    for (int kt = 0; kt < NTILES_K; kt++) {
        cp_async_wait_all();
        __syncthreads();   // tile kt visible to all; also fences prior reads
                           // of the buffer the next prefetch overwrites

        if (kt + 1 < NTILES_K) {
            const float* gA2 = gA + (kt + 1) * BK;
            const float* gB2 = gB + (kt + 1) * BK;
            uint32_t dA = ((kt + 1) & 1) ? sA1 : sA0;
            uint32_t dB = ((kt + 1) & 1) ? sB1 : sB0;
            cp_async16(dA, gA2);
            cp_async16(dA + 16, gA2 + 4);
            cp_async16(dB, gB2);
            cp_async_commit();
        }

        const float* Ab = As[kt & 1];
        const float* Bb = Bs[kt & 1];

#pragma unroll
        for (int ks = 0; ks < BK; ks += 8) {
            uint32_t ah[2][4], al[2][4];
#pragma unroll
            for (int mt = 0; mt < 2; mt++) {
                int r0 = warp_m + mt * 16 + g;
                float x0 = Ab[r0 * ASTRIDE + ks + t];
                float x1 = Ab[(r0 + 8) * ASTRIDE + ks + t];
                float x2 = Ab[r0 * ASTRIDE + ks + t + 4];
                float x3 = Ab[(r0 + 8) * ASTRIDE + ks + t + 4];
                split_tf32(x0, ah[mt][0], al[mt][0]);
                split_tf32(x1, ah[mt][1], al[mt][1]);
                split_tf32(x2, ah[mt][2], al[mt][2]);
                split_tf32(x3, ah[mt][3], al[mt][3]);
            }
#pragma unroll
            for (int nt = 0; nt < 4; nt++) {
                int n0 = warp_n + nt * 8 + g;
                float y0 = Bb[n0 * ASTRIDE + ks + t];
                float y1 = Bb[n0 * ASTRIDE + ks + t + 4];
                uint32_t bh[2], bl[2];
                split_tf32(y0, bh[0], bl[0]);
                split_tf32(y1, bh[1], bl[1]);
#pragma unroll
                for (int mt = 0; mt < 2; mt++) {
                    mma_tf32(acc[mt][nt], al[mt], bh);
                    mma_tf32(acc[mt][nt], ah[mt], bl);
                    mma_tf32(acc[mt][nt], ah[mt], bh);
                }
            }
        }
        // no trailing __syncthreads: next iteration's wait+sync is the fence
    }

    // Epilogue: bias (hoisted, float2) + relu, float2 stores.
#pragma unroll
    for (int nt = 0; nt < 4; nt++) {
        int col = bn + warp_n + nt * 8 + 2 * t;
        float2 bi = *(const float2*)&bias[col];   // mt-invariant, 8B-aligned
#pragma unroll
        for (int mt = 0; mt < 2; mt++) {
            int row = bm + warp_m + mt * 16 + g;
            float f0 = acc[mt][nt][0] + bi.x;
            float f1 = acc[mt][nt][1] + bi.y;
            float f2 = acc[mt][nt][2] + bi.x;
            float f3 = acc[mt][nt][3] + bi.y;
            f0 = f0 > 0.0f ? f0 : 0.0f;
            f1 = f1 > 0.0f ? f1 : 0.0f;
            f2 = f2 > 0.0f ? f2 : 0.0f;
            f3 = f3 > 0.0f ? f3 : 0.0f;
            *(float2*)&C[(size_t)row * DIM + col]       = make_float2(f0, f1);
            *(float2*)&C[(size_t)(row + 8) * DIM + col] = make_float2(f2, f3);
        }
    }
}

// ---------------------------------------------------------------------------
// Quantum kernel helpers: packed 2x2 complex gate application.
// Packed amp a = (x, y); twin sw = (y, x). Gate entry e = { (ur,ur), (-ui,ui) }:
//   u*amp = e.x (.) a + e.y (.) sw      (lane: (ur x - ui y, ur y + ui x))
// ---------------------------------------------------------------------------
__device__ __forceinline__ void qpair(unsigned long long* a, unsigned long long* sw,
                                      int i0, int i1, const ulonglong2* E) {
    unsigned long long n0 = 0ull, n1 = 0ull;
    FMA_F32X2(n0, E[0].x, a[i0], n0);
    FMA_F32X2(n0, E[0].y, sw[i0], n0);
    FMA_F32X2(n0, E[1].x, a[i1], n0);
    FMA_F32X2(n0, E[1].y, sw[i1], n0);
    FMA_F32X2(n1, E[2].x, a[i0], n1);
    FMA_F32X2(n1, E[2].y, sw[i0], n1);
    FMA_F32X2(n1, E[3].x, a[i1], n1);
    FMA_F32X2(n1, E[3].y, sw[i1], n1);
    a[i0] = n0;
    a[i1] = n1;
    uint32_t lo, hi;
    UNPACK_F32X2(lo, hi, n0);
    PACK_F32X2(sw[i0], hi, lo);
    UNPACK_F32X2(lo, hi, n1);
    PACK_F32X2(sw[i1], hi, lo);
}

// Same but does NOT rebuild the swapped twins (use for the LAST gate of a
// pass, whose sw[] values are dead: hand-DCE).
__device__ __forceinline__ void qpair_last(unsigned long long* a, unsigned long long* sw,
                                           int i0, int i1, const ulonglong2* E) {
    unsigned long long n0 = 0ull, n1 = 0ull;
    FMA_F32X2(n0, E[0].x, a[i0], n0);
    FMA_F32X2(n0, E[0].y, sw[i0], n0);
    FMA_F32X2(n0, E[1].x, a[i1], n0);
    FMA_F32X2(n0, E[1].y, sw[i1], n0);
    FMA_F32X2(n1, E[2].x, a[i0], n1);
    FMA_F32X2(n1, E[2].y, sw[i0], n1);
    FMA_F32X2(n1, E[3].x, a[i1], n1);
    FMA_F32X2(n1, E[3].y, sw[i1], n1);
    a[i0] = n0;
    a[i1] = n1;
}

// Apply 3 single-qubit gates (local j bits 2,1,0) factored on 8 register amps.
__device__ __forceinline__ void qgate3(unsigned long long* a, unsigned long long* sw,
                                       const ulonglong2* sg /* 3 gates x 4 entries */) {
    ulonglong2 e[4];
    // gate on bit 2: pairs (j, j+4)
    e[0] = sg[0]; e[1] = sg[1]; e[2] = sg[2]; e[3] = sg[3];
#pragma unroll
    for (int j = 0; j < 4; j++) qpair(a, sw, j, j + 4, e);
    // gate on bit 1: pairs (j, j+2)
    e[0] = sg[4]; e[1] = sg[5]; e[2] = sg[6]; e[3] = sg[7];
    qpair(a, sw, 0, 2, e);
    qpair(a, sw, 1, 3, e);
    qpair(a, sw, 4, 6, e);
    qpair(a, sw, 5, 7, e);
    // gate on bit 0: pairs (j, j+1)  -- sw dead afterwards
    e[0] = sg[8]; e[1] = sg[9]; e[2] = sg[10]; e[3] = sg[11];
    qpair_last(a, sw, 0, 1, e);
    qpair_last(a, sw, 2, 3, e);
    qpair_last(a, sw, 4, 5, e);
    qpair_last(a, sw, 6, 7, e);
}

// ---------------------------------------------------------------------------
// Kernel 2: quantum circuit sim + Z expvals + post GEMM.
// TWO batch elements per CTA (256 threads; 128 per element). State in smem,
// stored under the PSISW bank swizzle. Per layer: 4 passes over bit-triples
// (9,8,7)/(6,5,4)/(3,2,1)/(0); gates applied FACTORED in registers.
// CNOT ring folded into the last pass's scattered writes (GF(2)-linear).
// Circuit-phase barriers are PER-ELEMENT named barriers.
// ---------------------------------------------------------------------------
__global__ __launch_bounds__(256)
void quantum_kernel(const float* __restrict__ h,
                    const float* __restrict__ qw,      // [4,10,3]
                    const float* __restrict__ Wpost,   // [64,10]
                    const float* __restrict__ bpost,   // [64]
                    float* __restrict__ out) {         // [BATCH,64]
    __shared__ float2     psi[2][DIM];
    __shared__ ulonglong2 sgx[N_LAYERS * N_QUBITS][4];  // packed 1q gate entries
    __shared__ uint32_t   Pcols[N_LAYERS][N_QUBITS];
    __shared__ float      red[8];
    __shared__ float      zred[8][N_QUBITS];
    __shared__ float      zfin[2][N_QUBITS];
    __shared__ float      sinv_sh[2];

    const int tid  = threadIdx.x;
    const int lane = tid & 31;
    const int wid  = tid >> 5;
    const int elem = tid >> 7;       // 0 or 1
    const int wt   = tid & 127;      // thread within element
    const int b0   = blockIdx.x * 2 + elem;

    unsigned long long* psi64 = (unsigned long long*)psi[elem];

    // --- gate setup: Rot(phi,theta,omega) = RZ(omega) RY(theta) RZ(phi) ---
    if (tid < N_LAYERS * N_QUBITS) {
        float phi = qw[tid * 3 + 0];
        float th  = qw[tid * 3 + 1];
        float om  = qw[tid * 3 + 2];
        float s, c;  sincosf(0.5f * th, &s, &c);
        float aa = 0.5f * (phi + om);
        float dd = 0.5f * (phi - om);
        float sa, ca; sincosf(aa, &sa, &ca);
        float sd, cd; sincosf(dd, &sd, &cd);
        float ur[4], ui[4];
        ur[0] =  ca * c;  ui[0] = -sa * c;   // U00 = e^{-i(phi+om)/2} cos
        ur[1] = -cd * s;  ui[1] = -sd * s;   // U01 = -e^{+i(phi-om)/2} sin
        ur[2] =  cd * s;  ui[2] = -sd * s;   // U10 = e^{-i(phi-om)/2} sin
        ur[3] =  ca * c;  ui[3] =  sa * c;   // U11 = e^{+i(phi+om)/2} cos
#pragma unroll
        for (int e = 0; e < 4; e++) {
            ulonglong2 ee;
            PACK_F32X2(ee.x, __float_as_uint(ur[e]), __float_as_uint(ur[e]));
            PACK_F32X2(ee.y, __float_as_uint(-ui[e]), __float_as_uint(ui[e]));
            sgx[tid][e] = ee;
        }
    }

    // --- CNOT-block permutation columns: Pcols[l][b] = P_l(1<<b) ---
    if (tid >= 64 && tid < 64 + N_LAYERS * N_QUBITS) {
        int s2 = tid - 64;
        int l = s2 / N_QUBITS, bpos = s2 % N_QUBITS;
        int r = (l % (N_QUBITS - 1)) + 1;
        uint32_t x = 1u << bpos;
#pragma unroll
        for (int w = 0; w < N_QUBITS; w++) {
            int t2 = w + r;
            if (t2 >= N_QUBITS) t2 -= N_QUBITS;
            x ^= ((x >> (9 - w)) & 1) << (9 - t2);
        }
        Pcols[l][bpos] = x;
    }

    // --- load amplitudes (group-0 ownership order), squared norm ---
    const float* hrow = h + (size_t)b0 * DIM;
    float v[8];
    float ss = 0.0f;
#pragma unroll
    for (int j = 0; j < 8; j++) {
        v[j] = hrow[(j << 7) | wt];
        ss = fmaf(v[j], v[j], ss);
    }
#pragma unroll
    for (int off = 16; off > 0; off >>= 1)
        ss += __shfl_down_sync(0xffffffffu, ss, off);
    if (lane == 0) red[wid] = ss;
    __syncthreads();   // CTA-wide: also publishes sgx + Pcols to both elements
    if (wt == 0)
        sinv_sh[elem] = 1.0f / sqrtf(red[elem * 4] + red[elem * 4 + 1] +
                                     red[elem * 4 + 2] + red[elem * 4 + 3]);
    __syncthreads();   // CTA-wide (cheap; only 2 of these total)

    unsigned long long a[8], sw[8];
    {
        float inv = sinv_sh[elem];
#pragma unroll
        for (int j = 0; j < 8; j++) {
            uint32_t xb = __float_as_uint(v[j] * inv);
            uint32_t zb = 0;
            PACK_F32X2(a[j], xb, zb);   // (x, 0)
            PACK_F32X2(sw[j], zb, xb);  // (0, x)
        }
    }

    // --- circuit: 4 layers x 4 passes (per-element barriers from here on) ---
#pragma unroll
    for (int l = 0; l < N_LAYERS; l++) {
        // group 0: j bits -> global bits (9,8,7), qubits 0,1,2
        if (l > 0) {
#pragma unroll
            for (int j = 0; j < 8; j++) {
                a[j] = psi64[PSISW((j << 7) | wt)];
                uint32_t lo, hi;
                UNPACK_F32X2(lo, hi, a[j]);
                PACK_F32X2(sw[j], hi, lo);
            }
        }
        qgate3(a, sw, &sgx[l * N_QUBITS + 0][0]);
#pragma unroll
        for (int j = 0; j < 8; j++) psi64[PSISW((j << 7) | wt)] = a[j];
        ELEM_BAR(elem);

        // group 1: bits (6,5,4), qubits 3,4,5
        {
            int lo4 = wt & 15, hi3 = wt >> 4;
#pragma unroll
            for (int j = 0; j < 8; j++) {
                int idx = (hi3 << 7) | (j << 4) | lo4;
                a[j] = psi64[PSISW(idx)];
                uint32_t lo, hi;
                UNPACK_F32X2(lo, hi, a[j]);
                PACK_F32X2(sw[j], hi, lo);
            }
            qgate3(a, sw, &sgx[l * N_QUBITS + 3][0]);
#pragma unroll
            for (int j = 0; j < 8; j++) psi64[PSISW((hi3 << 7) | (j << 4) | lo4)] = a[j];
        }
        ELEM_BAR(elem);

        // group 2: bits (3,2,1), qubits 6,7,8
        {
            int lo1 = wt & 1, hi6 = wt >> 1;
#pragma unroll
            for (int j = 0; j < 8; j++) {
                int idx = (hi6 << 4) | (j << 1) | lo1;
                a[j] = psi64[PSISW(idx)];
                uint32_t lo, hi;
                UNPACK_F32X2(lo, hi, a[j]);
                PACK_F32X2(sw[j], hi, lo);
            }
            qgate3(a, sw, &sgx[l * N_QUBITS + 6][0]);
#pragma unroll
            for (int j = 0; j < 8; j++) psi64[PSISW((hi6 << 4) | (j << 1) | lo1)] = a[j];
        }
        ELEM_BAR(elem);

        // group 3: bit 0, qubit 9; then CNOT-permutation scatter
        {
#pragma unroll
            for (int j = 0; j < 8; j++) {
                a[j] = psi64[PSISW(wt * 8 + j)];
                uint32_t lo, hi;
                UNPACK_F32X2(lo, hi, a[j]);
                PACK_F32X2(sw[j], hi, lo);
            }
            ulonglong2 e[4];
            e[0] = sgx[l * N_QUBITS + 9][0];
            e[1] = sgx[l * N_QUBITS + 9][1];
            e[2] = sgx[l * N_QUBITS + 9][2];
            e[3] = sgx[l * N_QUBITS + 9][3];
            qpair_last(a, sw, 0, 1, e);
            qpair_last(a, sw, 2, 3, e);
            qpair_last(a, sw, 4, 5, e);
            qpair_last(a, sw, 6, 7, e);

            // dst(wt*8 + j) = P(wt<<3) ^ (j&1?p0) ^ (j&2?p1) ^ (j&4?p2)
            uint32_t Pb = 0;
#pragma unroll
            for (int bb = 0; bb < 7; bb++)
                if ((wt >> bb) & 1) Pb ^= Pcols[l][bb + 3];
            uint32_t p0 = Pcols[l][0];
            uint32_t p1 = Pcols[l][1];
            uint32_t p2 = Pcols[l][2];
            ELEM_BAR(elem);   // all reads done before scattered writes
            psi64[PSISW(Pb)]                = a[0];
            psi64[PSISW(Pb ^ p0)]           = a[1];
            psi64[PSISW(Pb ^ p1)]           = a[2];
            psi64[PSISW(Pb ^ p1 ^ p0)]      = a[3];
            psi64[PSISW(Pb ^ p2)]           = a[4];
            psi64[PSISW(Pb ^ p2 ^ p0)]      = a[5];
            psi64[PSISW(Pb ^ p2 ^ p1)]      = a[6];
            psi64[PSISW(Pb ^ p2 ^ p1 ^ p0)] = a[7];
            ELEM_BAR(elem);
        }
    }

    // --- PauliZ expectation values ---
    // Thread owns i = wt*8 + j: i bits 2..0 = j, bits 9..3 = wt.
    float sall = 0.0f, sb2 = 0.0f, sb1 = 0.0f, sb0 = 0.0f;
#pragma unroll
    for (int j = 0; j < 8; j++) {
        float2 am = psi[elem][PSISW(wt * 8 + j)];
        float p = fmaf(am.x, am.x, am.y * am.y);
        sall += p;
        sb2 += (j & 4) ? -p : p;
        sb1 += (j & 2) ? -p : p;
        sb0 += (j & 1) ? -p : p;
    }
    float z[N_QUBITS];
#pragma unroll
    for (int q = 0; q < 7; q++)
        z[q] = ((wt >> (6 - q)) & 1) ? -sall : sall;
    z[7] = sb2;
    z[8] = sb1;
    z[9] = sb0;
#pragma unroll
    for (int q = 0; q < N_QUBITS; q++)
#pragma unroll
        for (int off = 16; off > 0; off >>= 1)
            z[q] += __shfl_down_sync(0xffffffffu, z[q], off);
    if (lane == 0) {
#pragma unroll
        for (int q = 0; q < N_QUBITS; q++) zred[wid][q] = z[q];
    }
    ELEM_BAR(elem);
    if (wt < N_QUBITS) {
        int wbase = elem * 4;
        zfin[elem][wt] = zred[wbase][wt] + zred[wbase + 1][wt] +
                         zred[wbase + 2][wt] + zred[wbase + 3][wt];
    }
    ELEM_BAR(elem);

    // --- post linear: out[b0, :] = z @ Wpost^T + bpost ---
    if (wt < OUT_F) {
        float o = bpost[wt];
#pragma unroll
        for (int q = 0; q < N_QUBITS; q++)
            o = fmaf(zfin[elem][q], Wpost[wt * N_QUBITS + q], o);
        out[(size_t)b0 * OUT_F + wt] = o;
    }
}

// ---------------------------------------------------------------------------
extern "C" void kernel_launch(void* const* d_in, const int* in_sizes, int n_in,
                              void* d_out, int out_size) {
    const float* x      = (const float*)d_in[0];  // [4096,512]
    const float* W_pre  = (const float*)d_in[1];  // [1024,512]
    const float* b_pre  = (const float*)d_in[2];  // [1024]
    const float* q_w    = (const float*)d_in[3];  // [4,10,3]
    const float* W_post = (const float*)d_in[4];  // [64,10]
    const float* b_post = (const float*)d_in[5];  // [64]
    float* out = (float*)d_out;                   // [4096,64]

    float* h = nullptr;
    cudaGetSymbolAddress((void**)&h, g_h);

    dim3 g1(DIM / BN, BATCH / BM);   // (16, 32)
    gemm_relu_tc_kernel<<<g1, 256>>>(x, W_pre, b_pre, h);

    quantum_kernel<<<BATCH / 2, 256>>>(h, q_w, W_post, b_post, out);
}

// round 15
// speedup vs baseline: 1.3773x; 1.3773x over previous
#include <cuda_runtime.h>
#include <math.h>
#include <stdint.h>

#define N_QUBITS 10
#define N_LAYERS 4
#define DIM 1024
#define IN_F 512
#define OUT_F 64
#define BATCH 4096

// Scratch for the intermediate h = relu(x @ W_pre^T + b_pre): 4096 x 1024 fp32 = 16 MB
__device__ float g_h[BATCH * DIM];

// ---------------------------------------------------------------------------
// f32x2 packed-math helpers (FFMA2: one issue slot, two FMAs)
// ---------------------------------------------------------------------------
#define PACK_F32X2(out, lo, hi) \
    asm("mov.b64 %0, {%1, %2};" : "=l"(out) : "r"(lo), "r"(hi))
#define UNPACK_F32X2(lo, hi, in) \
    asm("mov.b64 {%0, %1}, %2;" : "=r"(lo), "=r"(hi) : "l"(in))
#define FMA_F32X2(d, a, b, c) \
    asm("fma.rn.f32x2 %0, %1, %2, %3;" : "=l"(d) : "l"(a), "l"(b), "l"(c))

// Per-element named barrier: element e = warps 4e..4e+3 (128 threads each).
// Barrier 0 is reserved for __syncthreads (CTA-wide setup syncs).
#define ELEM_BAR(e) \
    asm volatile("bar.sync %0, %1;" :: "r"((e) + 1), "r"(128) : "memory")

// Bank-conflict swizzle for the psi state array (8B elements): fold address
// bits 6..4 into bits 3..1. Involution (sw(sw(i)) == i), pure layout change.
#define PSISW(i) ((i) ^ (((i) >> 3) & 0x0E))

// ---------------------------------------------------------------------------
// bf16x2 split helpers.
// Split fp32 x into bf16 hi (truncation: top 16 bits) + bf16 lo (rounded
// remainder). x - hi_trunc is exact in fp32; lo rounding error ~2^-17|x|.
// Packs PAIRS (k, k+1) directly into the bf16x2 registers mma wants:
// lo 16 bits = element k, hi 16 bits = element k+1.
// ---------------------------------------------------------------------------
__device__ __forceinline__ void split_bf16x2(float x0, float x1,
                                             uint32_t& hi, uint32_t& lo) {
    uint32_t u0 = __float_as_uint(x0);
    uint32_t u1 = __float_as_uint(x1);
    // hi pack: {u1[31:16], u0[31:16]} in one PRMT
    asm("prmt.b32 %0, %1, %2, 0x7632;" : "=r"(hi) : "r"(u0), "r"(u1));
    float h0 = __uint_as_float(u0 & 0xFFFF0000u);
    float h1 = __uint_as_float(u1 & 0xFFFF0000u);
    float l0 = x0 - h0;   // exact
    float l1 = x1 - h1;   // exact
    asm("cvt.rn.bf16x2.f32 %0, %1, %2;" : "=r"(lo) : "f"(l1), "f"(l0));
}

// D(16x8) += A(16x16) * B(16x8), bf16 inputs, fp32 accumulate.
__device__ __forceinline__ void mma_bf16(float* d, const uint32_t* a, const uint32_t* b) {
    asm volatile(
        "mma.sync.aligned.m16n8k16.row.col.f32.bf16.bf16.f32 "
        "{%0,%1,%2,%3}, {%4,%5,%6,%7}, {%8,%9}, {%0,%1,%2,%3};"
        : "+f"(d[0]), "+f"(d[1]), "+f"(d[2]), "+f"(d[3])
        : "r"(a[0]), "r"(a[1]), "r"(a[2]), "r"(a[3]), "r"(b[0]), "r"(b[1]));
}

__device__ __forceinline__ void cp_async16(uint32_t smem_addr, const void* gptr) {
    asm volatile("cp.async.cg.shared.global [%0], [%1], 16;" ::"r"(smem_addr), "l"(gptr));
}
__device__ __forceinline__ void cp_async_commit() {
    asm volatile("cp.async.commit_group;");
}
__device__ __forceinline__ void cp_async_wait_all() {
    asm volatile("cp.async.wait_group 0;");
}

// ---------------------------------------------------------------------------
// Kernel 1: fused GEMM + bias + ReLU via bf16x2 3-term tensor-core mma.
// C[4096,1024] = relu(A[4096,512] @ W[1024,512]^T + bias).
// CTA tile 128(M) x 64(N), BK=16, 256 threads (8 warps, warp tile 32x32).
// m16n8k16 bf16 mma: HALF the mma + LDS instructions of the tf32 k8 path.
// cp.async double-buffered smem, ASTRIDE=24 (96B rows: 16B-aligned cp.async
// dst, conflict-free float2 fragment loads).
// Split: C += Alo*Bhi + Ahi*Blo + Ahi*Bhi  (error ~2^-16 << 1e-3).
// ---------------------------------------------------------------------------
#define BM 128
#define BN 64
#define BK 16
#define ASTRIDE 24
#define NTILES_K (IN_F / BK)   // 32

__global__ __launch_bounds__(256, 2)
void gemm_relu_tc_kernel(const float* __restrict__ A,
                         const float* __restrict__ B,
                         const float* __restrict__ bias,
                         float* __restrict__ C) {
    __shared__ float As[2][BM * ASTRIDE];   // 2 x 12 KB
    __shared__ float Bs[2][BN * ASTRIDE];   // 2 x  6 KB

    const int tid  = threadIdx.x;
    const int lane = tid & 31;
    const int wid  = tid >> 5;
    const int g    = lane >> 2;   // groupID (0..7)
    const int t    = lane & 3;    // threadID_in_group (0..3)

    const int bm = blockIdx.y * BM;
    const int bn = blockIdx.x * BN;

    const int warp_m = (wid & 3) * 32;
    const int warp_n = (wid >> 2) * 32;

    const int arow = tid >> 1;
    const int ac4  = (tid & 1) * 8;
    const int brow = tid >> 2;
    const int bc4  = (tid & 3) * 4;

    const float* gA = A + (size_t)(bm + arow) * IN_F + ac4;
    const float* gB = B + (size_t)(bn + brow) * IN_F + bc4;

    uint32_t sA0 = (uint32_t)__cvta_generic_to_shared(&As[0][arow * ASTRIDE + ac4]);
    uint32_t sA1 = (uint32_t)__cvta_generic_to_shared(&As[1][arow * ASTRIDE + ac4]);
    uint32_t sB0 = (uint32_t)__cvta_generic_to_shared(&Bs[0][brow * ASTRIDE + bc4]);
    uint32_t sB1 = (uint32_t)__cvta_generic_to_shared(&Bs[1][brow * ASTRIDE + bc4]);

    float acc[2][4][4];
#pragma unroll
    for (int i = 0; i < 2; i++)
#pragma unroll
        for (int j = 0; j < 4; j++)
#pragma unroll
            for (int c = 0; c < 4; c++) acc[i][j][c] = 0.0f;

    cp_async16(sA0, gA);
    cp_async16(sA0 + 16, gA + 4);
    cp_async16(sB0, gB);
    cp_async_commit();

    for (int kt = 0; kt < NTILES_K; kt++) {
        cp_async_wait_all();
        __syncthreads();   // tile kt visible; also fences prior-iter reads

        if (kt + 1 < NTILES_K) {
            const float* gA2 = gA + (kt + 1) * BK;
            const float* gB2 = gB + (kt + 1) * BK;
            uint32_t dA = ((kt + 1) & 1) ? sA1 : sA0;
            uint32_t dB = ((kt + 1) & 1) ? sB1 : sB0;
            cp_async16(dA, gA2);
            cp_async16(dA + 16, gA2 + 4);
            cp_async16(dB, gB2);
            cp_async_commit();
        }

        const float* Ab = As[kt & 1];
        const float* Bb = Bs[kt & 1];

        // A fragments: a0=(g,2t),(g,2t+1); a1=(g+8,..); a2=(g,2t+8..); a3=(g+8,2t+8..)
        uint32_t ah[2][4], al[2][4];
#pragma unroll
        for (int mt = 0; mt < 2; mt++) {
            int r0 = warp_m + mt * 16 + g;
            float2 p0 = *(const float2*)&Ab[r0 * ASTRIDE + 2 * t];
            float2 p1 = *(const float2*)&Ab[(r0 + 8) * ASTRIDE + 2 * t];
            float2 p2 = *(const float2*)&Ab[r0 * ASTRIDE + 2 * t + 8];
            float2 p3 = *(const float2*)&Ab[(r0 + 8) * ASTRIDE + 2 * t + 8];
            split_bf16x2(p0.x, p0.y, ah[mt][0], al[mt][0]);
            split_bf16x2(p1.x, p1.y, ah[mt][1], al[mt][1]);
            split_bf16x2(p2.x, p2.y, ah[mt][2], al[mt][2]);
            split_bf16x2(p3.x, p3.y, ah[mt][3], al[mt][3]);
        }
#pragma unroll
        for (int nt = 0; nt < 4; nt++) {
            int n0 = warp_n + nt * 8 + g;
            float2 q0 = *(const float2*)&Bb[n0 * ASTRIDE + 2 * t];
            float2 q1 = *(const float2*)&Bb[n0 * ASTRIDE + 2 * t + 8];
            uint32_t bh[2], bl[2];
            split_bf16x2(q0.x, q0.y, bh[0], bl[0]);
            split_bf16x2(q1.x, q1.y, bh[1], bl[1]);
#pragma unroll
            for (int mt = 0; mt < 2; mt++) {
                mma_bf16(acc[mt][nt], al[mt], bh);   // correction terms first
                mma_bf16(acc[mt][nt], ah[mt], bl);
                mma_bf16(acc[mt][nt], ah[mt], bh);   // main term
            }
        }
        // no trailing __syncthreads: next iteration's wait+sync is the fence
    }

    // Epilogue: bias (hoisted, float2) + relu, float2 stores.
#pragma unroll
    for (int nt = 0; nt < 4; nt++) {
        int col = bn + warp_n + nt * 8 + 2 * t;
        float2 bi = *(const float2*)&bias[col];
#pragma unroll
        for (int mt = 0; mt < 2; mt++) {
            int row = bm + warp_m + mt * 16 + g;
            float f0 = acc[mt][nt][0] + bi.x;
            float f1 = acc[mt][nt][1] + bi.y;
            float f2 = acc[mt][nt][2] + bi.x;
            float f3 = acc[mt][nt][3] + bi.y;
            f0 = f0 > 0.0f ? f0 : 0.0f;
            f1 = f1 > 0.0f ? f1 : 0.0f;
            f2 = f2 > 0.0f ? f2 : 0.0f;
            f3 = f3 > 0.0f ? f3 : 0.0f;
            *(float2*)&C[(size_t)row * DIM + col]       = make_float2(f0, f1);
            *(float2*)&C[(size_t)(row + 8) * DIM + col] = make_float2(f2, f3);
        }
    }
}

// ---------------------------------------------------------------------------
// Quantum kernel helpers: packed 2x2 complex gate application.
// ---------------------------------------------------------------------------
__device__ __forceinline__ void qpair(unsigned long long* a, unsigned long long* sw,
                                      int i0, int i1, const ulonglong2* E) {
    unsigned long long n0 = 0ull, n1 = 0ull;
    FMA_F32X2(n0, E[0].x, a[i0], n0);
    FMA_F32X2(n0, E[0].y, sw[i0], n0);
    FMA_F32X2(n0, E[1].x, a[i1], n0);
    FMA_F32X2(n0, E[1].y, sw[i1], n0);
    FMA_F32X2(n1, E[2].x, a[i0], n1);
    FMA_F32X2(n1, E[2].y, sw[i0], n1);
    FMA_F32X2(n1, E[3].x, a[i1], n1);
    FMA_F32X2(n1, E[3].y, sw[i1], n1);
    a[i0] = n0;
    a[i1] = n1;
    uint32_t lo, hi;
    UNPACK_F32X2(lo, hi, n0);
    PACK_F32X2(sw[i0], hi, lo);
    UNPACK_F32X2(lo, hi, n1);
    PACK_F32X2(sw[i1], hi, lo);
}

__device__ __forceinline__ void qpair_last(unsigned long long* a, unsigned long long* sw,
                                           int i0, int i1, const ulonglong2* E) {
    unsigned long long n0 = 0ull, n1 = 0ull;
    FMA_F32X2(n0, E[0].x, a[i0], n0);
    FMA_F32X2(n0, E[0].y, sw[i0], n0);
    FMA_F32X2(n0, E[1].x, a[i1], n0);
    FMA_F32X2(n0, E[1].y, sw[i1], n0);
    FMA_F32X2(n1, E[2].x, a[i0], n1);
    FMA_F32X2(n1, E[2].y, sw[i0], n1);
    FMA_F32X2(n1, E[3].x, a[i1], n1);
    FMA_F32X2(n1, E[3].y, sw[i1], n1);
    a[i0] = n0;
    a[i1] = n1;
}

__device__ __forceinline__ void qgate3(unsigned long long* a, unsigned long long* sw,
                                       const ulonglong2* sg) {
    ulonglong2 e[4];
    e[0] = sg[0]; e[1] = sg[1]; e[2] = sg[2]; e[3] = sg[3];
#pragma unroll
    for (int j = 0; j < 4; j++) qpair(a, sw, j, j + 4, e);
    e[0] = sg[4]; e[1] = sg[5]; e[2] = sg[6]; e[3] = sg[7];
    qpair(a, sw, 0, 2, e);
    qpair(a, sw, 1, 3, e);
    qpair(a, sw, 4, 6, e);
    qpair(a, sw, 5, 7, e);
    e[0] = sg[8]; e[1] = sg[9]; e[2] = sg[10]; e[3] = sg[11];
    qpair_last(a, sw, 0, 1, e);
    qpair_last(a, sw, 2, 3, e);
    qpair_last(a, sw, 4, 5, e);
    qpair_last(a, sw, 6, 7, e);
}

// ---------------------------------------------------------------------------
// Kernel 2: quantum circuit sim + Z expvals + post GEMM.
// launch_bounds(256,3): cap regs so 3 CTAs/SM fit (occ 23.6% -> ~35%;
// profile showed latency-bound: issue=43%, L1=69%).
// ---------------------------------------------------------------------------
__global__ __launch_bounds__(256, 3)
void quantum_kernel(const float* __restrict__ h,
                    const float* __restrict__ qw,      // [4,10,3]
                    const float* __restrict__ Wpost,   // [64,10]
                    const float* __restrict__ bpost,   // [64]
                    float* __restrict__ out) {         // [BATCH,64]
    __shared__ float2     psi[2][DIM];
    __shared__ ulonglong2 sgx[N_LAYERS * N_QUBITS][4];
    __shared__ uint32_t   Pcols[N_LAYERS][N_QUBITS];
    __shared__ float      red[8];
    __shared__ float      zred[8][N_QUBITS];
    __shared__ float      zfin[2][N_QUBITS];
    __shared__ float      sinv_sh[2];

    const int tid  = threadIdx.x;
    const int lane = tid & 31;
    const int wid  = tid >> 5;
    const int elem = tid >> 7;       // 0 or 1
    const int wt   = tid & 127;      // thread within element
    const int b0   = blockIdx.x * 2 + elem;

    unsigned long long* psi64 = (unsigned long long*)psi[elem];

    // --- gate setup: Rot(phi,theta,omega) = RZ(omega) RY(theta) RZ(phi) ---
    if (tid < N_LAYERS * N_QUBITS) {
        float phi = qw[tid * 3 + 0];
        float th  = qw[tid * 3 + 1];
        float om  = qw[tid * 3 + 2];
        float s, c;  sincosf(0.5f * th, &s, &c);
        float aa = 0.5f * (phi + om);
        float dd = 0.5f * (phi - om);
        float sa, ca; sincosf(aa, &sa, &ca);
        float sd, cd; sincosf(dd, &sd, &cd);
        float ur[4], ui[4];
        ur[0] =  ca * c;  ui[0] = -sa * c;
        ur[1] = -cd * s;  ui[1] = -sd * s;
        ur[2] =  cd * s;  ui[2] = -sd * s;
        ur[3] =  ca * c;  ui[3] =  sa * c;
#pragma unroll
        for (int e = 0; e < 4; e++) {
            ulonglong2 ee;
            PACK_F32X2(ee.x, __float_as_uint(ur[e]), __float_as_uint(ur[e]));
            PACK_F32X2(ee.y, __float_as_uint(-ui[e]), __float_as_uint(ui[e]));
            sgx[tid][e] = ee;
        }
    }

    // --- CNOT-block permutation columns: Pcols[l][b] = P_l(1<<b) ---
    if (tid >= 64 && tid < 64 + N_LAYERS * N_QUBITS) {
        int s2 = tid - 64;
        int l = s2 / N_QUBITS, bpos = s2 % N_QUBITS;
        int r = (l % (N_QUBITS - 1)) + 1;
        uint32_t x = 1u << bpos;
#pragma unroll
        for (int w = 0; w < N_QUBITS; w++) {
            int t2 = w + r;
            if (t2 >= N_QUBITS) t2 -= N_QUBITS;
            x ^= ((x >> (9 - w)) & 1) << (9 - t2);
        }
        Pcols[l][bpos] = x;
    }

    // --- load amplitudes (group-0 ownership order), squared norm ---
    const float* hrow = h + (size_t)b0 * DIM;
    float v[8];
    float ss = 0.0f;
#pragma unroll
    for (int j = 0; j < 8; j++) {
        v[j] = hrow[(j << 7) | wt];
        ss = fmaf(v[j], v[j], ss);
    }
#pragma unroll
    for (int off = 16; off > 0; off >>= 1)
        ss += __shfl_down_sync(0xffffffffu, ss, off);
    if (lane == 0) red[wid] = ss;
    __syncthreads();   // CTA-wide: also publishes sgx + Pcols
    if (wt == 0)
        sinv_sh[elem] = 1.0f / sqrtf(red[elem * 4] + red[elem * 4 + 1] +
                                     red[elem * 4 + 2] + red[elem * 4 + 3]);
    __syncthreads();

    unsigned long long a[8], sw[8];
    {
        float inv = sinv_sh[elem];
#pragma unroll
        for (int j = 0; j < 8; j++) {
            uint32_t xb = __float_as_uint(v[j] * inv);
            uint32_t zb = 0;
            PACK_F32X2(a[j], xb, zb);   // (x, 0)
            PACK_F32X2(sw[j], zb, xb);  // (0, x)
        }
    }

    // --- circuit: 4 layers x 4 passes ---
#pragma unroll
    for (int l = 0; l < N_LAYERS; l++) {
        // group 0: bits (9,8,7), qubits 0,1,2
        if (l > 0) {
#pragma unroll
            for (int j = 0; j < 8; j++) {
                a[j] = psi64[PSISW((j << 7) | wt)];
                uint32_t lo, hi;
                UNPACK_F32X2(lo, hi, a[j]);
                PACK_F32X2(sw[j], hi, lo);
            }
        }
        qgate3(a, sw, &sgx[l * N_QUBITS + 0][0]);
#pragma unroll
        for (int j = 0; j < 8; j++) psi64[PSISW((j << 7) | wt)] = a[j];
        ELEM_BAR(elem);

        // group 1: bits (6,5,4), qubits 3,4,5
        {
            int lo4 = wt & 15, hi3 = wt >> 4;
#pragma unroll
            for (int j = 0; j < 8; j++) {
                int idx = (hi3 << 7) | (j << 4) | lo4;
                a[j] = psi64[PSISW(idx)];
                uint32_t lo, hi;
                UNPACK_F32X2(lo, hi, a[j]);
                PACK_F32X2(sw[j], hi, lo);
            }
            qgate3(a, sw, &sgx[l * N_QUBITS + 3][0]);
#pragma unroll
            for (int j = 0; j < 8; j++) psi64[PSISW((hi3 << 7) | (j << 4) | lo4)] = a[j];
        }
        ELEM_BAR(elem);

        // group 2: bits (3,2,1), qubits 6,7,8
        {
            int lo1 = wt & 1, hi6 = wt >> 1;
#pragma unroll
            for (int j = 0; j < 8; j++) {
                int idx = (hi6 << 4) | (j << 1) | lo1;
                a[j] = psi64[PSISW(idx)];
                uint32_t lo, hi;
                UNPACK_F32X2(lo, hi, a[j]);
                PACK_F32X2(sw[j], hi, lo);
            }
            qgate3(a, sw, &sgx[l * N_QUBITS + 6][0]);
#pragma unroll
            for (int j = 0; j < 8; j++) psi64[PSISW((hi6 << 4) | (j << 1) | lo1)] = a[j];
        }
        ELEM_BAR(elem);

        // group 3: bit 0, qubit 9; then CNOT-permutation scatter
        {
#pragma unroll
            for (int j = 0; j < 8; j++) {
                a[j] = psi64[PSISW(wt * 8 + j)];
                uint32_t lo, hi;
                UNPACK_F32X2(lo, hi, a[j]);
                PACK_F32X2(sw[j], hi, lo);
            }
            ulonglong2 e[4];
            e[0] = sgx[l * N_QUBITS + 9][0];
            e[1] = sgx[l * N_QUBITS + 9][1];
            e[2] = sgx[l * N_QUBITS + 9][2];
            e[3] = sgx[l * N_QUBITS + 9][3];
            qpair_last(a, sw, 0, 1, e);
            qpair_last(a, sw, 2, 3, e);
            qpair_last(a, sw, 4, 5, e);
            qpair_last(a, sw, 6, 7, e);

            uint32_t Pb = 0;
#pragma unroll
            for (int bb = 0; bb < 7; bb++)
                if ((wt >> bb) & 1) Pb ^= Pcols[l][bb + 3];
            uint32_t p0 = Pcols[l][0];
            uint32_t p1 = Pcols[l][1];
            uint32_t p2 = Pcols[l][2];
            ELEM_BAR(elem);   // all reads done before scattered writes
            psi64[PSISW(Pb)]                = a[0];
            psi64[PSISW(Pb ^ p0)]           = a[1];
            psi64[PSISW(Pb ^ p1)]           = a[2];
            psi64[PSISW(Pb ^ p1 ^ p0)]      = a[3];
            psi64[PSISW(Pb ^ p2)]           = a[4];
            psi64[PSISW(Pb ^ p2 ^ p0)]      = a[5];
            psi64[PSISW(Pb ^ p2 ^ p1)]      = a[6];
            psi64[PSISW(Pb ^ p2 ^ p1 ^ p0)] = a[7];
            ELEM_BAR(elem);
        }
    }

    // --- PauliZ expectation values ---
    float sall = 0.0f, sb2 = 0.0f, sb1 = 0.0f, sb0 = 0.0f;
#pragma unroll
    for (int j = 0; j < 8; j++) {
        float2 am = psi[elem][PSISW(wt * 8 + j)];
        float p = fmaf(am.x, am.x, am.y * am.y);
        sall += p;
        sb2 += (j & 4) ? -p : p;
        sb1 += (j & 2) ? -p : p;
        sb0 += (j & 1) ? -p : p;
    }
    float z[N_QUBITS];
#pragma unroll
    for (int q = 0; q < 7; q++)
        z[q] = ((wt >> (6 - q)) & 1) ? -sall : sall;
    z[7] = sb2;
    z[8] = sb1;
    z[9] = sb0;
#pragma unroll
    for (int q = 0; q < N_QUBITS; q++)
#pragma unroll
        for (int off = 16; off > 0; off >>= 1)
            z[q] += __shfl_down_sync(0xffffffffu, z[q], off);
    if (lane == 0) {
#pragma unroll
        for (int q = 0; q < N_QUBITS; q++) zred[wid][q] = z[q];
    }
    ELEM_BAR(elem);
    if (wt < N_QUBITS) {
        int wbase = elem * 4;
        zfin[elem][wt] = zred[wbase][wt] + zred[wbase + 1][wt] +
                         zred[wbase + 2][wt] + zred[wbase + 3][wt];
    }
    ELEM_BAR(elem);

    // --- post linear: out[b0, :] = z @ Wpost^T + bpost ---
    if (wt < OUT_F) {
        float o = bpost[wt];
#pragma unroll
        for (int q = 0; q < N_QUBITS; q++)
            o = fmaf(zfin[elem][q], Wpost[wt * N_QUBITS + q], o);
        out[(size_t)b0 * OUT_F + wt] = o;
    }
}

// ---------------------------------------------------------------------------
extern "C" void kernel_launch(void* const* d_in, const int* in_sizes, int n_in,
                              void* d_out, int out_size) {
    const float* x      = (const float*)d_in[0];  // [4096,512]
    const float* W_pre  = (const float*)d_in[1];  // [1024,512]
    const float* b_pre  = (const float*)d_in[2];  // [1024]
    const float* q_w    = (const float*)d_in[3];  // [4,10,3]
    const float* W_post = (const float*)d_in[4];  // [64,10]
    const float* b_post = (const float*)d_in[5];  // [64]
    float* out = (float*)d_out;                   // [4096,64]

    float* h = nullptr;
    cudaGetSymbolAddress((void**)&h, g_h);

    dim3 g1(DIM / BN, BATCH / BM);   // (16, 32)
    gemm_relu_tc_kernel<<<g1, 256>>>(x, W_pre, b_pre, h);

    quantum_kernel<<<BATCH / 2, 256>>>(h, q_w, W_post, b_post, out);
}